// round 15
// baseline (speedup 1.0000x reference)
#include <cuda_runtime.h>
#include <math.h>

#define BB   32
#define TT   512
#define CC   4233
#define UU   64
#define LABT 129
#define ROWE 68                           // 64 odds + blank@64 + pad (16B rows)
#define PADV (-3.4028234663852886e38f)   // jnp.finfo(float32).min
#define FULL 0xffffffffu
#define PD   4                            // prefetch distance

// compact gathered emissions: [B*T + PD pad rows][ROWE]
__device__ __align__(16) float g_emit[((size_t)BB * TT + PD) * ROWE];
// scratch: Viterbi path indices per (b,t)
__device__ unsigned short g_wi[BB * TT];

// ---------------------------------------------------------------------------
// Phase 1: gather. Row: [0..63]=emit(label_u), [64]=emit(blank).
// ---------------------------------------------------------------------------
__global__ void gather_kernel(const float* __restrict__ logit,
                              const int*   __restrict__ label,
                              const int*   __restrict__ blankp)
{
    const int blank = blankp ? *blankp : 0;
    unsigned idx = blockIdx.x * blockDim.x + threadIdx.x;
    const unsigned total = (unsigned)BB * TT * 65;
    if (idx >= total) return;

    unsigned j  = idx % 65;            // 0..63 label slots, 64 = blank
    unsigned bt = idx / 65;            // b*T + t  (b = bt>>9)

    int c;
    if (j < 64) {
        int l = label[j * BB + (bt >> 9)];
        if (l == blank) l = -1;        // pad sentinel, wraps like jnp % C
        c = l % CC; if (c < 0) c += CC;
    } else {
        c = blank % CC; if (c < 0) c += CC;
    }
    g_emit[(size_t)bt * ROWE + j] = logit[(size_t)bt * CC + (unsigned)c];
}

// ---------------------------------------------------------------------------
// Phase 2: TWO batches per 128-thread block, interleaved per step so the
// smem round-trip + barrier is amortized over 2 batch-steps. Lane gl owns
// position j=gl+1 of both batches; j=0 is lane 0's exact blank running sum.
// Arithmetic per batch identical to the R14-passing kernel.
// ---------------------------------------------------------------------------
__global__ __launch_bounds__(128, 1)
void dp_kernel(const int* __restrict__ label,
               const int* __restrict__ blankp,
               unsigned short* __restrict__ wi_out,
               float* __restrict__ out_loss)
{
    __shared__ float          bufA[2][132], bufB[2][132];  // [0]=pad, [j+1]=dp[j]
    __shared__ unsigned char  dsmA[TT / 4][128], dsmB[TT / 4][128];
    __shared__ unsigned short wiA[TT], wiB[TT];

    const int gl    = threadIdx.x;             // 0..127, owns j = gl+1
    const int bA    = 2 * blockIdx.x;
    const int bB    = bA + 1;
    const int blank = blankp ? *blankp : 0;

    // cond per position per batch (odd j = even gl uses labels; even j: true)
    const int myu  = gl >> 1;
    const int labA = label[myu * BB + bA];
    const int labB = label[myu * BB + bB];
    const int lpA  = (myu > 0) ? label[(myu - 1) * BB + bA] : blank;
    const int lpB  = (myu > 0) ? label[(myu - 1) * BB + bB] : blank;
    const int ejA  = (labA == blank) ? -1 : labA;
    const int ejB  = (labB == blank) ? -1 : labB;
    const int ejpA = (myu > 0) ? ((lpA == blank) ? -1 : lpA) : -1;
    const int ejpB = (myu > 0) ? ((lpB == blank) ? -1 : lpB) : -1;
    const bool condA = (gl & 1) ? true : ((ejA == blank) || (ejA == ejpA));
    const bool condB = (gl & 1) ? true : ((ejB == blank) || (ejB == ejpB));

    // emission pointers
    const float* baseA = g_emit + (size_t)bA * TT * ROWE;
    const float* baseB = g_emit + (size_t)bB * TT * ROWE;
    const int    off   = (gl & 1) ? 64 : (gl >> 1);
    const float* peA = baseA + off;
    const float* peB = baseB + off;
    const float* pbA = baseA + 64;             // blank streams (lane 0's z)
    const float* pbB = baseB + 64;

    float eA[PD], eB[PD], ebA[PD], ebB[PD];
    #pragma unroll
    for (int tp = 0; tp < PD; tp++) {
        eA[tp] = peA[0];  peA += ROWE;
        eB[tp] = peB[0];  peB += ROWE;
        if (gl == 0) { ebA[tp] = pbA[0]; ebB[tp] = pbB[0]; }
        pbA += ROWE; pbB += ROWE;
    }

    // ---- t = 0 init ----
    float zA   = (gl == 0) ? ebA[0] : 0.0f;
    float zB   = (gl == 0) ? ebB[0] : 0.0f;
    float myvA = (gl == 0) ? eA[0] : PADV;
    float myvB = (gl == 0) ? eB[0] : PADV;
    // refill consumed slot 0 with row PD (pipeline phase)
    eA[0] = peA[0];  peA += ROWE;
    eB[0] = peB[0];  peB += ROWE;
    if (gl == 0) { ebA[0] = pbA[0]; ebB[0] = pbB[0]; }
    pbA += ROWE; pbB += ROWE;

    bufA[0][0] = PADV; bufA[1][0] = PADV;
    bufB[0][0] = PADV; bufB[1][0] = PADV;
    bufA[0][gl + 2] = myvA;
    bufB[0][gl + 2] = myvB;
    if (gl == 0) { bufA[0][1] = zA; bufB[0][1] = zB; }
    unsigned daccA = 0, daccB = 0;
    __syncthreads();

    // ---- main recurrence: 2 batch-steps per barrier ----
    #pragma unroll 2
    for (int t = 1; t < TT; t++) {
        const int c = t & 1, p = c ^ 1, s = t & 3;
        const float evA = eA[s];
        const float evB = eB[s];
        eA[s] = peA[0];  peA += ROWE;          // prefetch t+PD (padded, safe)
        eB[s] = peB[0];  peB += ROWE;
        float ebvA = 0.0f, ebvB = 0.0f;
        if (gl == 0) {
            ebvA = ebA[s]; ebA[s] = pbA[0];
            ebvB = ebB[s]; ebB[s] = pbB[0];
        }
        pbA += ROWE; pbB += ROWE;

        const float a1A = bufA[p][gl + 1];     // dp_prev[j-1]
        const float a2A = bufA[p][gl];         // dp_prev[j-2]
        const float a1B = bufB[p][gl + 1];
        const float a2B = bufB[p][gl];

        // batch A LSE (R14-exact ops)
        const float x2A = condA ? PADV : a2A;
        const float hiA = fmaxf(myvA, a1A);
        const float loA = fminf(myvA, a1A);
        const float mA  = fmaxf(hiA, x2A);
        const float seA = fminf(hiA, fmaxf(loA, x2A));
        const float thA = fminf(loA, x2A);
        const float smA = 1.0f + __expf(seA - mA) + __expf(thA - mA);
        const unsigned dA = (x2A > hiA) ? 2u : ((a1A > myvA) ? 1u : 0u);
        myvA = evA + mA + __logf(smA);

        // batch B LSE (independent chain — overlaps A's latency)
        const float x2B = condB ? PADV : a2B;
        const float hiB = fmaxf(myvB, a1B);
        const float loB = fminf(myvB, a1B);
        const float mB  = fmaxf(hiB, x2B);
        const float seB = fminf(hiB, fmaxf(loB, x2B));
        const float thB = fminf(loB, x2B);
        const float smB = 1.0f + __expf(seB - mB) + __expf(thB - mB);
        const unsigned dB = (x2B > hiB) ? 2u : ((a1B > myvB) ? 1u : 0u);
        myvB = evB + mB + __logf(smB);

        bufA[c][gl + 2] = myvA;
        bufB[c][gl + 2] = myvB;
        if (gl == 0) {
            zA += ebvA; bufA[c][1] = zA;
            zB += ebvB; bufB[c][1] = zB;
        }

        daccA |= dA << (2 * s);
        daccB |= dB << (2 * s);
        if (s == 3) {
            dsmA[t >> 2][gl] = (unsigned char)daccA; daccA = 0;
            dsmB[t >> 2][gl] = (unsigned char)daccB; daccB = 0;
        }
        __syncthreads();
    }

    // ---- yl per batch ----
    const int cntA = __syncthreads_count(((gl & 1) == 0) && (labA != blank));
    const int cntB = __syncthreads_count(((gl & 1) == 0) && (labB != blank));
    const int ylA = 2 * cntA + 1;
    const int ylB = 2 * cntB + 1;

    auto widx = [&](int idx) { return ((idx % LABT) + LABT) % LABT; };
    const float* lastA = bufA[(TT - 1) & 1];
    const float* lastB = bufB[(TT - 1) & 1];
    const float dvA1 = lastA[widx(ylA - 1) + 1];
    const float dvA2 = lastA[widx(ylA - 2) + 1];
    const float dvB1 = lastB[widx(ylB - 1) + 1];
    const float dvB2 = lastB[widx(ylB - 2) + 1];

    // ---- concurrent speculative backtrack: warp 0 -> A, warp 1 -> B ----
    if (gl < 32) {
        int wi = (dvA1 > dvA2) ? (ylA - 1) : (ylA - 2);
        int t  = TT - 1;
        while (t >= 1) {
            const int tt = t - gl;
            const bool valid = (tt >= 1);
            int d = 0;
            if (valid && wi > 0)
                d = (int)((dsmA[tt >> 2][wi - 1] >> (2 * (tt & 3))) & 3u);
            const unsigned nz = __ballot_sync(FULL, valid && (d != 0));
            const int nvalid = (t < 32) ? t : 32;
            const int first  = nz ? (__ffs(nz) - 1) : 32;
            const int adv    = (first + 1 < nvalid) ? (first + 1) : nvalid;
            if (gl < adv) wiA[tt] = (unsigned short)wi;
            const int dfirst = __shfl_sync(FULL, d, (first < 31) ? first : 31);
            if (first < nvalid) wi -= dfirst;
            t -= adv;
        }
        if (gl == 0) {
            wiA[0] = (unsigned short)wi;
            const float mm  = fmaxf(dvA1, dvA2);
            const float lse = mm + log1pf(expf(-fabsf(dvA1 - dvA2)));
            if (out_loss) out_loss[bA] = -2.0f * lse / (float)(ylA - 1);
        }
    } else if (gl < 64) {
        const int ln = gl - 32;
        int wi = (dvB1 > dvB2) ? (ylB - 1) : (ylB - 2);
        int t  = TT - 1;
        while (t >= 1) {
            const int tt = t - ln;
            const bool valid = (tt >= 1);
            int d = 0;
            if (valid && wi > 0)
                d = (int)((dsmB[tt >> 2][wi - 1] >> (2 * (tt & 3))) & 3u);
            const unsigned nz = __ballot_sync(FULL, valid && (d != 0));
            const int nvalid = (t < 32) ? t : 32;
            const int first  = nz ? (__ffs(nz) - 1) : 32;
            const int adv    = (first + 1 < nvalid) ? (first + 1) : nvalid;
            if (ln < adv) wiB[tt] = (unsigned short)wi;
            const int dfirst = __shfl_sync(FULL, d, (first < 31) ? first : 31);
            if (first < nvalid) wi -= dfirst;
            t -= adv;
        }
        if (ln == 0) {
            wiB[0] = (unsigned short)wi;
            const float mm  = fmaxf(dvB1, dvB2);
            const float lse = mm + log1pf(expf(-fabsf(dvB1 - dvB2)));
            if (out_loss) out_loss[bB] = -2.0f * lse / (float)(ylB - 1);
        }
    }
    __syncthreads();

    for (int t = gl; t < TT; t += 128) {
        wi_out[bA * TT + t] = wiA[t];
        wi_out[bB * TT + t] = wiB[t];
    }
}

// ---------------------------------------------------------------------------
// One warp per (b,t) row: broadcast wi, contiguous one-hot stores
// ---------------------------------------------------------------------------
__global__ void align_kernel(const unsigned short* __restrict__ wi,
                             float* __restrict__ out)
{
    const int w    = (blockIdx.x * blockDim.x + threadIdx.x) >> 5;  // row = b*T+t
    const int lane = threadIdx.x & 31;
    if (w >= BB * TT) return;
    const int wiv = (int)wi[w];
    float* row = out + (size_t)w * LABT;
    #pragma unroll
    for (int j = lane; j < LABT; j += 32)
        row[j] = (j == wiv) ? 1.0f : 0.0f;
}

// ---------------------------------------------------------------------------
extern "C" void kernel_launch(void* const* d_in, const int* in_sizes, int n_in,
                              void* d_out, int out_size)
{
    const float* logit  = (const float*)d_in[0];
    const int*   label  = (const int*)d_in[1];
    const int*   blankp = (n_in >= 3) ? (const int*)d_in[2] : nullptr;

    float* out = (float*)d_out;
    const size_t align_elems = (size_t)BB * TT * LABT;   // 2,113,536
    float* out_loss = ((size_t)out_size >= align_elems + BB) ? (out + align_elems)
                                                             : nullptr;

    unsigned short* wi;
    cudaGetSymbolAddress((void**)&wi, g_wi);

    const int gtotal = BB * TT * 65;
    gather_kernel<<<(gtotal + 255) / 256, 256>>>(logit, label, blankp);
    dp_kernel<<<BB / 2, 128>>>(label, blankp, wi, out_loss);
    align_kernel<<<(BB * TT * 32 + 255) / 256, 256>>>(wi, out);
}

// round 17
// speedup vs baseline: 3.2435x; 3.2435x over previous
#include <cuda_runtime.h>
#include <math.h>

#define BB   32
#define TT   512
#define CC   4233
#define UU   64
#define LABT 129
#define ROWE 68                           // 64 odds + blank@64 + pad (16B rows)
#define PADV (-3.4028234663852886e38f)   // jnp.finfo(float32).min
#define FULL 0xffffffffu
#define BK   8                            // steps per block-iteration
#define NBLK (TT / BK)                    // 64

// compact gathered emissions: [B*T + BK pad rows][ROWE]
__device__ __align__(16) float g_emit[((size_t)BB * TT + BK) * ROWE];
// scratch: Viterbi path indices per (b,t)
__device__ unsigned short g_wi[BB * TT];

// ---------------------------------------------------------------------------
// Phase 1: gather. Row: [0..63]=emit(label_u), [64]=emit(blank).
// ---------------------------------------------------------------------------
__global__ void gather_kernel(const float* __restrict__ logit,
                              const int*   __restrict__ label,
                              const int*   __restrict__ blankp)
{
    const int blank = blankp ? *blankp : 0;
    unsigned idx = blockIdx.x * blockDim.x + threadIdx.x;
    const unsigned total = (unsigned)BB * TT * 65;
    if (idx >= total) return;

    unsigned j  = idx % 65;            // 0..63 label slots, 64 = blank
    unsigned bt = idx / 65;            // b*T + t  (b = bt>>9)

    int c;
    if (j < 64) {
        int l = label[j * BB + (bt >> 9)];
        if (l == blank) l = -1;        // pad sentinel, wraps like jnp % C
        c = l % CC; if (c < 0) c += CC;
    } else {
        c = blank % CC; if (c < 0) c += CC;
    }
    g_emit[(size_t)bt * ROWE + j] = logit[(size_t)bt * CC + (unsigned)c];
}

// ---------------------------------------------------------------------------
// Phase 2: skewed-wavefront DP. 128 threads, warp w owns j=32w+1..32w+32 in
// registers; neighbors via shfl_up; seam lane reads prev-warp history from
// smem. Warp w processes time-block i-w at iteration i -> one barrier per
// 8 steps. Arithmetic identical to the R14-passing kernel.
// ---------------------------------------------------------------------------
__global__ __launch_bounds__(128, 1)
void dp_kernel(const int* __restrict__ label,
               const int* __restrict__ blankp,
               unsigned short* __restrict__ wi_out,
               float* __restrict__ out_loss)
{
    __shared__ float          hist[3][TT][2]; // seam history: [w][t][{j=32w+31,32w+32}]
    __shared__ float          buf[132];       // final dp row ([0]=pad, [j+1]=dp[j])
    __shared__ unsigned char  dsm[TT / 4][128];
    __shared__ unsigned short wi_sm[TT];

    const int gl    = threadIdx.x;            // owns j = gl+1
    const int w     = gl >> 5;                // warp id 0..3
    const int lane  = gl & 31;
    const int b     = blockIdx.x;
    const int blank = blankp ? *blankp : 0;

    // cond (R14-identical): odd j (even gl) from labels; even j: true
    const int myu  = gl >> 1;
    const int lab  = label[myu * BB + b];
    const int labp = (myu > 0) ? label[(myu - 1) * BB + b] : blank;
    const int ej   = (lab  == blank) ? -1 : lab;
    const int ejp  = (myu > 0) ? ((labp == blank) ? -1 : labp) : -1;
    const bool cond = (gl & 1) ? true : ((ej == blank) || (ej == ejp));

    // emission streams (R14 layout)
    const float* __restrict__ base = g_emit + (size_t)b * TT * ROWE;
    const float* pe = base + ((gl & 1) ? 64 : (gl >> 1));
    const float* pz = base + 64;              // blank stream (lane0/warp0 z)
    const bool zl = (w == 0 && lane == 0);

    float bufE[BK], bufZ[BK];
    #pragma unroll
    for (int k = 0; k < BK; k++) {
        bufE[k] = pe[0];  pe += ROWE;
        if (zl) { bufZ[k] = pz[0]; }  pz += ROWE;
    }

    float myv = PADV, z = 0.0f;
    unsigned dacc = 0;

    // one DP step (R14-exact LSE ops)
    auto do_step = [&](int t, float e, float ebz) {
        float a1 = __shfl_up_sync(FULL, myv, 1);
        float a2 = __shfl_up_sync(FULL, myv, 2);
        if (lane == 0) {
            a1 = (w == 0) ? z    : hist[w - 1][t - 1][1];
            a2 = (w == 0) ? PADV : hist[w - 1][t - 1][0];
        }
        const float x2 = cond ? PADV : a2;
        const float hi = fmaxf(myv, a1);
        const float lo = fminf(myv, a1);
        const float m_ = fmaxf(hi, x2);
        const float se = fminf(hi, fmaxf(lo, x2));
        const float th = fminf(lo, x2);
        const float sm = 1.0f + __expf(se - m_) + __expf(th - m_);
        const unsigned d = (x2 > hi) ? 2u : ((a1 > myv) ? 1u : 0u);
        myv = e + m_ + __logf(sm);
        if (zl) z += ebz;                       // z_t = z_{t-1} + eb_t (exact)
        if (w < 3 && lane >= 30) hist[w][t][lane - 30] = myv;
        dacc |= d << (2 * (t & 3));
        if ((t & 3) == 3) { dsm[t >> 2][gl] = (unsigned char)dacc; dacc = 0; }
    };

    const int NITER = NBLK + 3;               // 64 blocks + 3-warp skew
    for (int i = 0; i < NITER; i++) {
        const int m = i - w;                   // warp-uniform block index
        if (m >= 0 && m < NBLK) {
            if (m == 0) {
                // ---- t = 0 init ----
                if (zl) z = bufZ[0];
                myv = zl ? bufE[0] : PADV;     // dp[1](0) on (w0,l0), else PADV
                if (w < 3 && lane >= 30) hist[w][0][lane - 30] = myv;
                bufE[0] = pe[0];  pe += ROWE;  // refill slot 0 with row 8
                if (zl) { bufZ[0] = pz[0]; }  pz += ROWE;
                #pragma unroll
                for (int k = 1; k < BK; k++) {
                    const float e = bufE[k], eb = bufZ[k];
                    bufE[k] = pe[0];  pe += ROWE;
                    if (zl) { bufZ[k] = pz[0]; }  pz += ROWE;
                    do_step(k, e, eb);
                }
            } else {
                const int t0 = m * BK;
                #pragma unroll
                for (int k = 0; k < BK; k++) {
                    const float e = bufE[k], eb = bufZ[k];
                    bufE[k] = pe[0];  pe += ROWE;   // row t0+k+8 (padded, safe)
                    if (zl) { bufZ[k] = pz[0]; }  pz += ROWE;
                    do_step(t0 + k, e, eb);
                }
            }
        }
        __syncthreads();
    }

    // ---- publish final dp row ----
    buf[gl + 2] = myv;
    if (zl) { buf[0] = PADV; buf[1] = z; }
    __syncthreads();

    // ---- yl ----
    const int cnt = __syncthreads_count(((gl & 1) == 0) && (lab != blank));
    const int yl  = 2 * cnt + 1;

    auto widx = [&](int idx) { return ((idx % LABT) + LABT) % LABT; };
    const float dv1 = buf[widx(yl - 1) + 1];
    const float dv2 = buf[widx(yl - 2) + 1];

    // ---- warp-0 speculative backtrack (wi non-increasing) ----
    if (gl < 32) {
        int wi = (dv1 > dv2) ? (yl - 1) : (yl - 2);
        int t  = TT - 1;
        while (t >= 1) {
            const int tt = t - gl;
            const bool valid = (tt >= 1);
            int d = 0;
            if (valid && wi > 0)
                d = (int)((dsm[tt >> 2][wi - 1] >> (2 * (tt & 3))) & 3u);
            const unsigned nz = __ballot_sync(FULL, valid && (d != 0));
            const int nvalid = (t < 32) ? t : 32;
            const int first  = nz ? (__ffs(nz) - 1) : 32;
            const int adv    = (first + 1 < nvalid) ? (first + 1) : nvalid;
            if (gl < adv) wi_sm[tt] = (unsigned short)wi;
            const int dfirst = __shfl_sync(FULL, d, (first < 31) ? first : 31);
            if (first < nvalid) wi -= dfirst;
            t -= adv;
        }
        if (gl == 0) {
            wi_sm[0] = (unsigned short)wi;
            const float mm  = fmaxf(dv1, dv2);
            const float lse = mm + log1pf(expf(-fabsf(dv1 - dv2)));
            if (out_loss) out_loss[b] = -2.0f * lse / (float)(yl - 1);
        }
    }
    __syncthreads();

    for (int t = gl; t < TT; t += 128)
        wi_out[b * TT + t] = wi_sm[t];
}

// ---------------------------------------------------------------------------
// One warp per (b,t) row: broadcast wi, contiguous one-hot stores
// ---------------------------------------------------------------------------
__global__ void align_kernel(const unsigned short* __restrict__ wi,
                             float* __restrict__ out)
{
    const int w    = (blockIdx.x * blockDim.x + threadIdx.x) >> 5;  // row = b*T+t
    const int lane = threadIdx.x & 31;
    if (w >= BB * TT) return;
    const int wiv = (int)wi[w];
    float* row = out + (size_t)w * LABT;
    #pragma unroll
    for (int j = lane; j < LABT; j += 32)
        row[j] = (j == wiv) ? 1.0f : 0.0f;
}

// ---------------------------------------------------------------------------
extern "C" void kernel_launch(void* const* d_in, const int* in_sizes, int n_in,
                              void* d_out, int out_size)
{
    const float* logit  = (const float*)d_in[0];
    const int*   label  = (const int*)d_in[1];
    const int*   blankp = (n_in >= 3) ? (const int*)d_in[2] : nullptr;

    float* out = (float*)d_out;
    const size_t align_elems = (size_t)BB * TT * LABT;   // 2,113,536
    float* out_loss = ((size_t)out_size >= align_elems + BB) ? (out + align_elems)
                                                             : nullptr;

    unsigned short* wi;
    cudaGetSymbolAddress((void**)&wi, g_wi);

    const int gtotal = BB * TT * 65;
    gather_kernel<<<(gtotal + 255) / 256, 256>>>(logit, label, blankp);
    dp_kernel<<<BB, 128>>>(label, blankp, wi, out_loss);
    align_kernel<<<(BB * TT * 32 + 255) / 256, 256>>>(wi, out);
}